// round 11
// baseline (speedup 1.0000x reference)
#include <cuda_runtime.h>
#include <cuda_bf16.h>
#include <math_constants.h>

#define NMAX 50000
#define EMAX 1250000
#define FEAT 64
#define NCLS 10
#define NPB  8          // nodes per warp batch in l1trans

#define SCAN_NB 250
#define SCAN_CH 200     // SCAN_NB * SCAN_CH = 50000 >= NMAX

typedef unsigned long long ull;

#define FFMA2(d, a, b) asm("fma.rn.f32x2 %0, %1, %2, %0;" : "+l"(d) : "l"(a), "l"(b))
#define FADD2(d, a)    asm("add.rn.f32x2 %0, %0, %1;"     : "+l"(d) : "l"(a))
#define PACK2(d, x, y) asm("mov.b64 %0, {%1, %2};" : "=l"(d) : "f"(x), "f"(y))
#define UNPK2(x, y, d) asm("mov.b64 {%0, %1}, %2;" : "=f"(x), "=f"(y) : "l"(d))

__device__ int   g_deg[NMAX];
__device__ int   g_off[NMAX + 1];
__device__ int   g_rank[EMAX];
__device__ int   g_srcs[EMAX];
__device__ int   g_scan_state[SCAN_NB];
__device__ int   g_scan_ctr;
__device__ int   g_bar;
__device__ float g_mx[(size_t)NMAX * 2 * FEAT];  // interleaved (mean,x) pairs
__device__ float g_y[(size_t)NMAX * 16];   // W2_l @ x1, padded 10->16
__device__ float g_z[(size_t)NMAX * NCLS]; // W2_r @ x1 + b2
__device__ int   g_is64;

// ---------------------------------------------------------------------------
// hist: per-block dtype detect, histogram of dst into g_deg (assumed zero),
// per-edge rank capture, and scan-state reset.
// ---------------------------------------------------------------------------
__global__ void __launch_bounds__(256) hist_kernel(const void* ei, int E, int n) {
    __shared__ int sis64;
    int tid = threadIdx.x;
    if (tid < 32) {
        const long long* p = (const long long*)ei;
        int bad = 0;
        for (int j = tid; j < 64; j += 32) {
            long long v = p[j];
            if (v < 0 || v >= (long long)n) bad = 1;
        }
        bad = __any_sync(0xffffffffu, bad);
        if (tid == 0) sis64 = bad ? 0 : 1;
    }
    __syncthreads();
    int is64 = sis64;
    int e = blockIdx.x * 256 + tid;
    if (blockIdx.x == 0 && tid == 0) { g_is64 = is64; g_scan_ctr = 0; g_bar = 0; }
    if (e < SCAN_NB) g_scan_state[e] = 0;
    if (e >= E) return;
    int d;
    if (is64) d = (int)((const long long*)ei)[E + e];
    else      d = ((const int*)ei)[E + e];
    g_rank[e] = atomicAdd(&g_deg[d], 1);
}

// ---------------------------------------------------------------------------
// single-pass decoupled-lookback exclusive scan of g_deg -> g_off.
// Also zeroes g_deg and writes the g_off[n] = E sentinel.
// ---------------------------------------------------------------------------
__global__ void __launch_bounds__(256) scan_kernel(int n) {
    __shared__ int sh[256];
    __shared__ int sbid;
    __shared__ int sex;
    int t = threadIdx.x;
    if (t == 0) sbid = atomicAdd(&g_scan_ctr, 1);
    __syncthreads();
    int bid = sbid;
    int idx = bid * SCAN_CH + t;
    int v = (t < SCAN_CH && idx < n) ? g_deg[idx] : 0;
    sh[t] = v;
    __syncthreads();
    #pragma unroll
    for (int d = 1; d < 256; d <<= 1) {
        int u = (t >= d) ? sh[t - d] : 0;
        __syncthreads();
        sh[t] += u;
        __syncthreads();
    }
    int total = sh[255];
    if (t == 0) {
        if (bid == 0) {
            atomicExch(&g_scan_state[0], (2 << 30) | total);
            sex = 0;
        } else {
            atomicExch(&g_scan_state[bid], (1 << 30) | total);
            int ex = 0, j = bid - 1;
            while (true) {
                int st = atomicAdd(&g_scan_state[j], 0);
                int f = ((unsigned)st) >> 30;
                if (f == 0) continue;
                ex += st & 0x3FFFFFFF;
                if (f == 2) break;
                --j;
            }
            atomicExch(&g_scan_state[bid], (2 << 30) | (ex + total));
            sex = ex;
        }
    }
    __syncthreads();
    int ex = sex;
    if (t < SCAN_CH && idx < n) {
        g_off[idx] = ex + sh[t] - v;
        g_deg[idx] = 0;
    }
    if (bid == SCAN_NB - 1 && t == 0) g_off[n] = ex + total;
}

// ---------------------------------------------------------------------------
// Fused scatter + layer-1 gather with a software grid barrier.
// Phase 1: atomic-free scatter (pos = off[dst] + rank).
// Barrier: arrival counter; grid size == resident capacity (host-computed via
// cudaOccupancyMaxActiveBlocksPerMultiprocessor) so all blocks are resident.
// Phase 2: warp-per-node gather; writes interleaved (mean,x) float4 rows.
// ---------------------------------------------------------------------------
__global__ void __launch_bounds__(256) sgather_kernel(
    const void* ei, const float* __restrict__ feat, int E, int N)
{
    int tid = threadIdx.x;

    // ---- phase 1: scatter ----
    {
        int is64 = g_is64;
        for (int e = blockIdx.x * 256 + tid; e < E; e += gridDim.x * 256) {
            int s, d;
            if (is64) {
                const long long* p = (const long long*)ei;
                s = (int)p[e];
                d = (int)p[E + e];
            } else {
                const int* p = (const int*)ei;
                s = p[e];
                d = p[E + e];
            }
            g_srcs[g_off[d] + g_rank[e]] = s;
        }
    }

    // ---- grid barrier ----
    __threadfence();
    __syncthreads();
    if (tid == 0) {
        atomicAdd(&g_bar, 1);
        while (atomicAdd(&g_bar, 0) < (int)gridDim.x) __nanosleep(64);
    }
    __syncthreads();
    __threadfence();

    // ---- phase 2: gather ----
    int lane = tid & 31, w = tid >> 5;
    int wg = blockIdx.x * 8 + w;
    int nw = gridDim.x * 8;

    for (int i = wg; i < N; i += nw) {
        int base = g_off[i];
        int deg  = g_off[i + 1] - base;
        ull acc0, acc1;
        PACK2(acc0, 0.f, 0.f);
        PACK2(acc1, 0.f, 0.f);
        for (int j0 = 0; j0 < deg; j0 += 32) {
            int m = deg - j0; if (m > 32) m = 32;
            int s = (lane < m) ? g_srcs[base + j0 + lane] : 0;
            int j = 0;
            #pragma unroll 4
            for (; j + 1 < m; j += 2) {
                int sj0 = __shfl_sync(0xffffffffu, s, j);
                int sj1 = __shfl_sync(0xffffffffu, s, j + 1);
                ull v0 = *(const ull*)(feat + (size_t)sj0 * FEAT + 2 * lane);
                ull v1 = *(const ull*)(feat + (size_t)sj1 * FEAT + 2 * lane);
                FADD2(acc0, v0);
                FADD2(acc1, v1);
            }
            if (j < m) {
                int sj = __shfl_sync(0xffffffffu, s, j);
                ull v = *(const ull*)(feat + (size_t)sj * FEAT + 2 * lane);
                FADD2(acc0, v);
            }
        }
        FADD2(acc0, acc1);
        float ax, ay; UNPK2(ax, ay, acc0);
        float inv = 1.f / fmaxf((float)deg, 1.f);
        float2 xi = *(const float2*)(feat + (size_t)i * FEAT + 2 * lane);
        *(float4*)(g_mx + (size_t)i * 2 * FEAT + 4 * lane) =
            make_float4(ax * inv, xi.x, ay * inv, xi.y);
    }
}

// ---------------------------------------------------------------------------
// Fused layer-1 transform + layer-2 transform. NPB=8 nodes per warp per pass.
// Pass A (layer 1): x1 = relu(normalize(Wl@mean + b + Wr@x)), kept in smem.
// Pass B (layer 2): y = W2l@x1 (lanes 0..9), z = W2r@x1 + b2 (lanes 16..25).
// Staging: one LDG.128 per lane per node from interleaved g_mx.
// ---------------------------------------------------------------------------
__global__ void __launch_bounds__(256, 3) l1trans_kernel(
    const float* __restrict__ Wl,
    const float* __restrict__ b,
    const float* __restrict__ Wr,
    const float* __restrict__ W2l,
    const float* __restrict__ b2,
    const float* __restrict__ W2r,
    int N)
{
    extern __shared__ char dsm[];
    float4* sWa = (float4*)dsm;                 // 16KB
    float4* sWb = sWa + 32 * 32;                // 16KB
    float2* sW2 = (float2*)(sWb + 32 * 32);     // 8KB
    float2* sV  = sW2 + 32 * 32;                // 32KB: [8 warps][NPB*FEAT]

    int tid = threadIdx.x;
    for (int idx = tid; idx < 32 * 32; idx += 256) {
        int kk = idx >> 5, c = idx & 31;
        int k0 = 2 * kk, k1 = 2 * kk + 1;
        sWa[idx] = make_float4(Wl[c * FEAT + k0],        Wr[c * FEAT + k0],
                               Wl[c * FEAT + k1],        Wr[c * FEAT + k1]);
        sWb[idx] = make_float4(Wl[(c + 32) * FEAT + k0], Wr[(c + 32) * FEAT + k0],
                               Wl[(c + 32) * FEAT + k1], Wr[(c + 32) * FEAT + k1]);
        float2 w2 = make_float2(0.f, 0.f);
        if (c < NCLS)                      w2 = make_float2(W2l[c * FEAT + k0], W2l[c * FEAT + k1]);
        else if (c >= 16 && c < 16 + NCLS) w2 = make_float2(W2r[(c - 16) * FEAT + k0], W2r[(c - 16) * FEAT + k1]);
        sW2[idx] = w2;
    }
    __syncthreads();

    int lane = tid & 31, w = tid >> 5;
    int wg = blockIdx.x * 8 + w;
    int nw = gridDim.x * 8;
    float bias0 = b[lane], bias1 = b[lane + 32];
    float bias2 = (lane >= 16 && lane < 16 + NCLS) ? b2[lane - 16] : 0.f;

    const ulonglong2* sWaq = (const ulonglong2*)sWa;
    const ulonglong2* sWbq = (const ulonglong2*)sWb;
    const ull*        sW2q = (const ull*)sW2;
    float2* sVw = sV + w * (NPB * FEAT);
    const ulonglong2* sVq = (const ulonglong2*)sVw;   // [t*32 + kk]
    float* sXw = (float*)sVw;                          // pass-B reuse: [t*64 + k]

    for (int i0 = wg * NPB; i0 < N; i0 += nw * NPB) {
        // stage NPB nodes of (mean, x) into shared — one LDG.128 each
        #pragma unroll
        for (int t = 0; t < NPB; ++t) {
            int i = i0 + t;
            if (i >= N) break;
            float4 v = *(const float4*)(g_mx + (size_t)i * 2 * FEAT + 4 * lane);
            *(float4*)&sVw[t * FEAT + 2 * lane] = v;
        }
        __syncwarp();

        // ---- pass A: layer-1 transform ----
        ull p0[NPB], p1[NPB];
        #pragma unroll
        for (int t = 0; t < NPB; ++t) { PACK2(p0[t], bias0, 0.f); PACK2(p1[t], bias1, 0.f); }
        #pragma unroll
        for (int kk = 0; kk < 32; ++kk) {
            ulonglong2 wa = sWaq[kk * 32 + lane];
            ulonglong2 wb = sWbq[kk * 32 + lane];
            #pragma unroll
            for (int t = 0; t < NPB; ++t) {
                ulonglong2 v = sVq[t * 32 + kk];   // 16B broadcast
                FFMA2(p0[t], wa.x, v.x);
                FFMA2(p0[t], wa.y, v.y);
                FFMA2(p1[t], wb.x, v.x);
                FFMA2(p1[t], wb.y, v.y);
            }
        }
        __syncwarp();   // pass A reads of sV done before overwrite
        #pragma unroll
        for (int t = 0; t < NPB; ++t) {
            int i = i0 + t;
            if (i >= N) break;
            float a, bb, o0, o1;
            UNPK2(a, bb, p0[t]); o0 = a + bb;
            UNPK2(a, bb, p1[t]); o1 = a + bb;
            float ss = o0 * o0 + o1 * o1;
            #pragma unroll
            for (int d = 16; d; d >>= 1) ss += __shfl_xor_sync(0xffffffffu, ss, d);
            float innorm = 1.f / fmaxf(sqrtf(ss), 1e-12f);
            sXw[t * FEAT + lane]      = fmaxf(o0 * innorm, 0.f);
            sXw[t * FEAT + lane + 32] = fmaxf(o1 * innorm, 0.f);
        }
        __syncwarp();

        // ---- pass B: layer-2 transform on x1 rows in smem ----
        ull q[NPB];
        #pragma unroll
        for (int t = 0; t < NPB; ++t) PACK2(q[t], bias2, 0.f);
        #pragma unroll
        for (int kk = 0; kk < 32; ++kk) {
            ull w2 = sW2q[kk * 32 + lane];
            #pragma unroll
            for (int t = 0; t < NPB; ++t) {
                ull v = *(const ull*)&sXw[t * FEAT + 2 * kk];   // broadcast
                FFMA2(q[t], w2, v);
            }
        }
        #pragma unroll
        for (int t = 0; t < NPB; ++t) {
            int i = i0 + t;
            if (i >= N) break;
            float a, bb; UNPK2(a, bb, q[t]);
            float o = a + bb;
            if (lane < NCLS)                   g_y[(size_t)i * 16 + lane] = o;
            else if (lane < 16)                g_y[(size_t)i * 16 + lane] = 0.f;
            else if (lane < 16 + NCLS)         g_z[(size_t)i * NCLS + (lane - 16)] = o;
        }
        __syncwarp();
    }
}

// ---------------------------------------------------------------------------
// Layer 2 gather over 64B g_y rows + epilogue (normalize, log_softmax).
// Lanes 0-15 / 16-31 handle alternating edges; dual accumulators.
// ---------------------------------------------------------------------------
__global__ void __launch_bounds__(256) l2g_kernel(float* __restrict__ out, int N) {
    int tid = threadIdx.x;
    int lane = tid & 31, w = tid >> 5;
    int half = lane >> 4;
    int slot = lane & 15;
    int wg = blockIdx.x * 8 + w;
    int nw = gridDim.x * 8;

    for (int i = wg; i < N; i += nw) {
        int base = g_off[i];
        int deg  = g_off[i + 1] - base;
        float acca = 0.f, accb = 0.f;
        for (int j0 = 0; j0 < deg; j0 += 32) {
            int m = deg - j0; if (m > 32) m = 32;
            int s = (lane < m) ? g_srcs[base + j0 + lane] : 0;
            int np = (m + 1) >> 1;
            int p = 0;
            #pragma unroll 4
            for (; p + 1 < np; p += 2) {
                int ia = 2 * p + half;
                int ib = 2 * (p + 1) + half;
                int sa = __shfl_sync(0xffffffffu, s, ia);
                int sb = __shfl_sync(0xffffffffu, s, ib);
                float va = g_y[(size_t)sa * 16 + slot];
                float vb = g_y[(size_t)sb * 16 + slot];
                if (ia < m) acca += va;
                if (ib < m) accb += vb;
            }
            if (p < np) {
                int ia = 2 * p + half;
                int sa = __shfl_sync(0xffffffffu, s, ia);
                float va = g_y[(size_t)sa * 16 + slot];
                if (ia < m) acca += va;
            }
        }
        float acc = acca + accb;
        acc += __shfl_down_sync(0xffffffffu, acc, 16);
        float inv = 1.f / fmaxf((float)deg, 1.f);
        float o = acc * inv;
        if (lane < NCLS) o += g_z[(size_t)i * NCLS + lane];

        float ss = (lane < NCLS) ? o * o : 0.f;
        #pragma unroll
        for (int d = 16; d; d >>= 1) ss += __shfl_xor_sync(0xffffffffu, ss, d);
        float innorm = 1.f / fmaxf(sqrtf(ss), 1e-12f);
        o *= innorm;
        float mx = (lane < NCLS) ? o : -CUDART_INF_F;
        #pragma unroll
        for (int d = 16; d; d >>= 1) mx = fmaxf(mx, __shfl_xor_sync(0xffffffffu, mx, d));
        float ex = (lane < NCLS) ? expf(o - mx) : 0.f;
        float es = ex;
        #pragma unroll
        for (int d = 16; d; d >>= 1) es += __shfl_xor_sync(0xffffffffu, es, d);
        float lse = logf(es);
        if (lane < NCLS)
            out[(size_t)i * NCLS + lane] = (o - mx) - lse;
    }
}

extern "C" void kernel_launch(void* const* d_in, const int* in_sizes, int n_in,
                              void* d_out, int out_size) {
    const float* feat = (const float*)d_in[0];
    const void*  ei   = d_in[1];
    const float* W1l  = (const float*)d_in[2];
    const float* b1   = (const float*)d_in[3];
    const float* W1r  = (const float*)d_in[4];
    const float* W2l  = (const float*)d_in[5];
    const float* b2   = (const float*)d_in[6];
    const float* W2r  = (const float*)d_in[7];
    float* out = (float*)d_out;

    int N = in_sizes[0] / FEAT;
    int E = in_sizes[1] / 2;

    static int sg_grid = 0;
    const int TRANS_SMEM = 72 * 1024;
    if (!sg_grid) {
        cudaFuncSetAttribute(l1trans_kernel,
                             cudaFuncAttributeMaxDynamicSharedMemorySize, TRANS_SMEM);
        int bpm = 0, sms = 0;
        cudaOccupancyMaxActiveBlocksPerMultiprocessor(&bpm, sgather_kernel, 256, 0);
        cudaDeviceGetAttribute(&sms, cudaDevAttrMultiProcessorCount, 0);
        if (bpm < 1) bpm = 1;
        if (sms < 1) sms = 148;
        sg_grid = bpm * sms;   // == resident capacity -> grid barrier is safe
    }

    hist_kernel<<<(E + 255) / 256, 256>>>(ei, E, N);             // 1
    scan_kernel<<<SCAN_NB, 256>>>(N);                            // 2
    sgather_kernel<<<sg_grid, 256>>>(ei, feat, E, N);            // 3
    l1trans_kernel<<<444, 256, TRANS_SMEM>>>(W1l, b1, W1r,
                                             W2l, b2, W2r, N);   // 4 <- profiled
    l2g_kernel<<<1184, 256>>>(out, N);                           // 5
}

// round 17
// speedup vs baseline: 1.2982x; 1.2982x over previous
#include <cuda_runtime.h>
#include <cuda_bf16.h>
#include <math_constants.h>

#define NMAX 50000
#define EMAX 1250000
#define FEAT 64
#define NCLS 10

#define SCAN_NB 250
#define SCAN_CH 200     // SCAN_NB * SCAN_CH = 50000 >= NMAX

typedef unsigned int       u32;
typedef unsigned long long ull;

#define FFMA2(d, a, b) asm("fma.rn.f32x2 %0, %1, %2, %0;" : "+l"(d) : "l"(a), "l"(b))
#define FADD2(d, a)    asm("add.rn.f32x2 %0, %0, %1;"     : "+l"(d) : "l"(a))
#define PACK2(d, x, y) asm("mov.b64 %0, {%1, %2};" : "=l"(d) : "f"(x), "f"(y))
#define UNPK2(x, y, d) asm("mov.b64 {%0, %1}, %2;" : "=f"(x), "=f"(y) : "l"(d))

__device__ int   g_deg[NMAX];
__device__ int   g_off[NMAX + 1];
__device__ int   g_rank[EMAX];
__device__ int   g_srcs[EMAX];
__device__ int   g_scan_state[SCAN_NB];
__device__ int   g_scan_ctr;
__device__ float g_mx[(size_t)NMAX * 2 * FEAT];  // interleaved (mean,x) pairs
__device__ float g_y[(size_t)NMAX * 16];
__device__ float g_z[(size_t)NMAX * NCLS];
__device__ int   g_is64;

// ---------------------------------------------------------------------------
__global__ void __launch_bounds__(256) hist_kernel(const void* ei, int E, int n) {
    __shared__ int sis64;
    int tid = threadIdx.x;
    if (tid < 32) {
        const long long* p = (const long long*)ei;
        int bad = 0;
        for (int j = tid; j < 64; j += 32) {
            long long v = p[j];
            if (v < 0 || v >= (long long)n) bad = 1;
        }
        bad = __any_sync(0xffffffffu, bad);
        if (tid == 0) sis64 = bad ? 0 : 1;
    }
    __syncthreads();
    int is64 = sis64;
    int e = blockIdx.x * 256 + tid;
    if (blockIdx.x == 0 && tid == 0) { g_is64 = is64; g_scan_ctr = 0; }
    if (e < SCAN_NB) g_scan_state[e] = 0;
    if (e >= E) return;
    int d;
    if (is64) d = (int)((const long long*)ei)[E + e];
    else      d = ((const int*)ei)[E + e];
    g_rank[e] = atomicAdd(&g_deg[d], 1);
}

__global__ void __launch_bounds__(256) scan_kernel(int n) {
    __shared__ int sh[256];
    __shared__ int sbid;
    __shared__ int sex;
    int t = threadIdx.x;
    if (t == 0) sbid = atomicAdd(&g_scan_ctr, 1);
    __syncthreads();
    int bid = sbid;
    int idx = bid * SCAN_CH + t;
    int v = (t < SCAN_CH && idx < n) ? g_deg[idx] : 0;
    sh[t] = v;
    __syncthreads();
    #pragma unroll
    for (int d = 1; d < 256; d <<= 1) {
        int u = (t >= d) ? sh[t - d] : 0;
        __syncthreads();
        sh[t] += u;
        __syncthreads();
    }
    int total = sh[255];
    if (t == 0) {
        if (bid == 0) {
            atomicExch(&g_scan_state[0], (2 << 30) | total);
            sex = 0;
        } else {
            atomicExch(&g_scan_state[bid], (1 << 30) | total);
            int ex = 0, j = bid - 1;
            while (true) {
                int st = atomicAdd(&g_scan_state[j], 0);
                int f = ((unsigned)st) >> 30;
                if (f == 0) continue;
                ex += st & 0x3FFFFFFF;
                if (f == 2) break;
                --j;
            }
            atomicExch(&g_scan_state[bid], (2 << 30) | (ex + total));
            sex = ex;
        }
    }
    __syncthreads();
    int ex = sex;
    if (t < SCAN_CH && idx < n) {
        g_off[idx] = ex + sh[t] - v;
        g_deg[idx] = 0;
    }
    if (bid == SCAN_NB - 1 && t == 0) g_off[n] = ex + total;
}

__global__ void __launch_bounds__(256) scatter_kernel(const void* ei, int E) {
    int e = blockIdx.x * blockDim.x + threadIdx.x;
    if (e >= E) return;
    int s, d;
    if (g_is64) {
        const long long* p = (const long long*)ei;
        s = (int)p[e];
        d = (int)p[E + e];
    } else {
        const int* p = (const int*)ei;
        s = p[e];
        d = p[E + e];
    }
    g_srcs[g_off[d] + g_rank[e]] = s;
}

// ---------------------------------------------------------------------------
// Layer 1 gather: warp per node, writes interleaved (mean,x) float4 rows.
// ---------------------------------------------------------------------------
__global__ void __launch_bounds__(256) l1gather_kernel(
    const float* __restrict__ feat, int N)
{
    int tid = threadIdx.x;
    int lane = tid & 31, w = tid >> 5;
    int wg = blockIdx.x * 8 + w;
    int nw = gridDim.x * 8;

    for (int i = wg; i < N; i += nw) {
        int base = g_off[i];
        int deg  = g_off[i + 1] - base;
        ull acc0, acc1;
        PACK2(acc0, 0.f, 0.f);
        PACK2(acc1, 0.f, 0.f);
        for (int j0 = 0; j0 < deg; j0 += 32) {
            int m = deg - j0; if (m > 32) m = 32;
            int s = (lane < m) ? g_srcs[base + j0 + lane] : 0;
            int j = 0;
            #pragma unroll 4
            for (; j + 1 < m; j += 2) {
                int sj0 = __shfl_sync(0xffffffffu, s, j);
                int sj1 = __shfl_sync(0xffffffffu, s, j + 1);
                ull v0 = *(const ull*)(feat + (size_t)sj0 * FEAT + 2 * lane);
                ull v1 = *(const ull*)(feat + (size_t)sj1 * FEAT + 2 * lane);
                FADD2(acc0, v0);
                FADD2(acc1, v1);
            }
            if (j < m) {
                int sj = __shfl_sync(0xffffffffu, s, j);
                ull v = *(const ull*)(feat + (size_t)sj * FEAT + 2 * lane);
                FADD2(acc0, v);
            }
        }
        FADD2(acc0, acc1);
        float ax, ay; UNPK2(ax, ay, acc0);
        float inv = 1.f / fmaxf((float)deg, 1.f);
        float2 xi = *(const float2*)(feat + (size_t)i * FEAT + 2 * lane);
        *(float4*)(g_mx + (size_t)i * 2 * FEAT + 4 * lane) =
            make_float4(ax * inv, xi.x, ay * inv, xi.y);
    }
}

// ---------------------------------------------------------------------------
// mma.sync-based fused transform (HMMA, valid on target sm_103).
// Warp-tile = 16 nodes. Pass A: C[16x64] = A[16x128]@W^T via m16n8k16 bf16
// 3-term split. Epilogue: +b1, row L2-normalize (quad shfl), ReLU. Pass B:
// x1 fragments (already mma-A layout) @ W2^T (24 padded outputs) -> g_y/g_z.
// ---------------------------------------------------------------------------
__device__ __forceinline__ void mma_bf16(float* c, const u32* a, u32 b0, u32 b1) {
    asm volatile("mma.sync.aligned.m16n8k16.row.col.f32.bf16.bf16.f32 "
        "{%0,%1,%2,%3}, {%4,%5,%6,%7}, {%8,%9}, {%0,%1,%2,%3};"
        : "+f"(c[0]), "+f"(c[1]), "+f"(c[2]), "+f"(c[3])
        : "r"(a[0]), "r"(a[1]), "r"(a[2]), "r"(a[3]), "r"(b0), "r"(b1));
}
__device__ __forceinline__ void cvt_hilo(float fx, float fy, u32& h, u32& l) {
    __nv_bfloat162 hh = __floats2bfloat162_rn(fx, fy);
    float rx = fx - __bfloat162float(hh.x);
    float ry = fy - __bfloat162float(hh.y);
    __nv_bfloat162 ll = __floats2bfloat162_rn(rx, ry);
    h = *(u32*)&hh;
    l = *(u32*)&ll;
}
__device__ __forceinline__ void wout(int node, int col, float v) {
    if (col < NCLS) g_y[(size_t)node * 16 + col] = v;
    else if (col < 16) {
        g_y[(size_t)node * 16 + col] = 0.f;
        g_z[(size_t)node * NCLS + col - NCLS] = v;
    } else if (col < 2 * NCLS) {
        g_z[(size_t)node * NCLS + col - NCLS] = v;
    }
}

#define W1S 136   // halves per row (conflict-free: 68 words, 68%32=4)
#define W2S 72    // halves per row (36 words, 36%32=4)

__global__ void __launch_bounds__(128) l1mma_kernel(
    const float* __restrict__ W1l, const float* __restrict__ b1,
    const float* __restrict__ W1r, const float* __restrict__ W2l,
    const float* __restrict__ b2,  const float* __restrict__ W2r, int N)
{
    __shared__ __nv_bfloat16 sWhi[64 * W1S];
    __shared__ __nv_bfloat16 sWlo[64 * W1S];
    __shared__ __nv_bfloat16 sW2hi[24 * W2S];
    __shared__ __nv_bfloat16 sW2lo[24 * W2S];
    __shared__ float sB1[64];
    __shared__ float sB2[NCLS];

    int tid = threadIdx.x;
    // W1 interleaved: row c, col k: k even -> W1l[c][k/2], odd -> W1r[c][k/2]
    for (int idx = tid; idx < 64 * 128; idx += 128) {
        int c = idx >> 7, k = idx & 127;
        float v = (k & 1) ? W1r[c * FEAT + (k >> 1)] : W1l[c * FEAT + (k >> 1)];
        __nv_bfloat16 h = __float2bfloat16_rn(v);
        __nv_bfloat16 l = __float2bfloat16_rn(v - __bfloat162float(h));
        sWhi[c * W1S + k] = h;
        sWlo[c * W1S + k] = l;
    }
    // W2 rows 0..9 = W2l, 10..19 = W2r, 20..23 = 0
    for (int idx = tid; idx < 24 * 64; idx += 128) {
        int c = idx >> 6, k = idx & 63;
        float v = 0.f;
        if (c < NCLS)            v = W2l[c * FEAT + k];
        else if (c < 2 * NCLS)   v = W2r[(c - NCLS) * FEAT + k];
        __nv_bfloat16 h = __float2bfloat16_rn(v);
        __nv_bfloat16 l = __float2bfloat16_rn(v - __bfloat162float(h));
        sW2hi[c * W2S + k] = h;
        sW2lo[c * W2S + k] = l;
    }
    if (tid < 64) sB1[tid] = b1[tid];
    if (tid < NCLS) sB2[tid] = b2[tid];
    __syncthreads();

    int lane = tid & 31, wid = tid >> 5;
    int g = lane >> 2, tq = lane & 3;       // groupID / thread-in-group
    int wg = blockIdx.x * 4 + wid;
    int nw = gridDim.x * 4;
    int tiles = (N + 15) / 16;

    for (int T = wg; T < tiles; T += nw) {
        int base = T * 16;
        int n0 = base + g;     if (n0 > N - 1) n0 = N - 1;
        int n1 = base + g + 8; if (n1 > N - 1) n1 = N - 1;
        const float* r0 = g_mx + (size_t)n0 * 128;
        const float* r1 = g_mx + (size_t)n1 * 128;

        // ---- pass A ----
        float cA[8][4];
        #pragma unroll
        for (int n = 0; n < 8; ++n) {
            int c0 = n * 8 + tq * 2;
            cA[n][0] = sB1[c0]; cA[n][1] = sB1[c0 + 1];
            cA[n][2] = sB1[c0]; cA[n][3] = sB1[c0 + 1];
        }
        #pragma unroll
        for (int ks = 0; ks < 8; ++ks) {
            int k0 = ks * 16 + tq * 2;
            float2 f0 = *(const float2*)(r0 + k0);
            float2 f1 = *(const float2*)(r1 + k0);
            float2 f2 = *(const float2*)(r0 + k0 + 8);
            float2 f3 = *(const float2*)(r1 + k0 + 8);
            u32 ah[4], al[4];
            cvt_hilo(f0.x, f0.y, ah[0], al[0]);
            cvt_hilo(f1.x, f1.y, ah[1], al[1]);
            cvt_hilo(f2.x, f2.y, ah[2], al[2]);
            cvt_hilo(f3.x, f3.y, ah[3], al[3]);
            #pragma unroll
            for (int n = 0; n < 8; ++n) {
                const __nv_bfloat16* wh = sWhi + (n * 8 + g) * W1S + ks * 16 + tq * 2;
                const __nv_bfloat16* wl = sWlo + (n * 8 + g) * W1S + ks * 16 + tq * 2;
                u32 bh0 = *(const u32*)wh;
                u32 bh1 = *(const u32*)(wh + 8);
                u32 bl0 = *(const u32*)wl;
                u32 bl1 = *(const u32*)(wl + 8);
                mma_bf16(cA[n], ah, bh0, bh1);   // AhBh
                mma_bf16(cA[n], ah, bl0, bl1);   // AhBl
                mma_bf16(cA[n], al, bh0, bh1);   // AlBh
            }
        }
        // epilogue: row L2-normalize + ReLU (rows g and g+8 of this tile)
        float ss0 = 0.f, ss1 = 0.f;
        #pragma unroll
        for (int n = 0; n < 8; ++n) {
            ss0 += cA[n][0] * cA[n][0] + cA[n][1] * cA[n][1];
            ss1 += cA[n][2] * cA[n][2] + cA[n][3] * cA[n][3];
        }
        ss0 += __shfl_xor_sync(0xffffffffu, ss0, 1);
        ss0 += __shfl_xor_sync(0xffffffffu, ss0, 2);
        ss1 += __shfl_xor_sync(0xffffffffu, ss1, 1);
        ss1 += __shfl_xor_sync(0xffffffffu, ss1, 2);
        float in0 = 1.f / fmaxf(sqrtf(ss0), 1e-12f);
        float in1 = 1.f / fmaxf(sqrtf(ss1), 1e-12f);
        #pragma unroll
        for (int n = 0; n < 8; ++n) {
            cA[n][0] = fmaxf(cA[n][0] * in0, 0.f);
            cA[n][1] = fmaxf(cA[n][1] * in0, 0.f);
            cA[n][2] = fmaxf(cA[n][2] * in1, 0.f);
            cA[n][3] = fmaxf(cA[n][3] * in1, 0.f);
        }

        // ---- pass B: x1 fragments are already in mma-A layout ----
        float c2[3][4];
        #pragma unroll
        for (int n = 0; n < 3; ++n) {
            int c0 = n * 8 + tq * 2;
            float z0 = (c0 >= NCLS && c0 < 2 * NCLS)         ? sB2[c0 - NCLS]     : 0.f;
            float z1 = (c0 + 1 >= NCLS && c0 + 1 < 2 * NCLS) ? sB2[c0 + 1 - NCLS] : 0.f;
            c2[n][0] = z0; c2[n][1] = z1; c2[n][2] = z0; c2[n][3] = z1;
        }
        #pragma unroll
        for (int t = 0; t < 4; ++t) {
            u32 ah[4], al[4];
            cvt_hilo(cA[2 * t][0],     cA[2 * t][1],     ah[0], al[0]);  // row g,   k lo
            cvt_hilo(cA[2 * t][2],     cA[2 * t][3],     ah[1], al[1]);  // row g+8, k lo
            cvt_hilo(cA[2 * t + 1][0], cA[2 * t + 1][1], ah[2], al[2]);  // row g,   k hi
            cvt_hilo(cA[2 * t + 1][2], cA[2 * t + 1][3], ah[3], al[3]);  // row g+8, k hi
            #pragma unroll
            for (int n = 0; n < 3; ++n) {
                const __nv_bfloat16* wh = sW2hi + (n * 8 + g) * W2S + t * 16 + tq * 2;
                const __nv_bfloat16* wl = sW2lo + (n * 8 + g) * W2S + t * 16 + tq * 2;
                u32 bh0 = *(const u32*)wh;
                u32 bh1 = *(const u32*)(wh + 8);
                u32 bl0 = *(const u32*)wl;
                u32 bl1 = *(const u32*)(wl + 8);
                mma_bf16(c2[n], ah, bh0, bh1);
                mma_bf16(c2[n], ah, bl0, bl1);
                mma_bf16(c2[n], al, bh0, bh1);
            }
        }
        // write out
        int m0 = base + g, m1 = base + g + 8;
        #pragma unroll
        for (int n = 0; n < 3; ++n) {
            int c0 = n * 8 + tq * 2;
            if (m0 < N) { wout(m0, c0, c2[n][0]); wout(m0, c0 + 1, c2[n][1]); }
            if (m1 < N) { wout(m1, c0, c2[n][2]); wout(m1, c0 + 1, c2[n][3]); }
        }
    }
}

// ---------------------------------------------------------------------------
// Layer 2 gather over 64B g_y rows + epilogue (normalize, log_softmax).
// ---------------------------------------------------------------------------
__global__ void __launch_bounds__(256) l2g_kernel(float* __restrict__ out, int N) {
    int tid = threadIdx.x;
    int lane = tid & 31, w = tid >> 5;
    int half = lane >> 4;
    int slot = lane & 15;
    int wg = blockIdx.x * 8 + w;
    int nw = gridDim.x * 8;

    for (int i = wg; i < N; i += nw) {
        int base = g_off[i];
        int deg  = g_off[i + 1] - base;
        float acca = 0.f, accb = 0.f;
        for (int j0 = 0; j0 < deg; j0 += 32) {
            int m = deg - j0; if (m > 32) m = 32;
            int s = (lane < m) ? g_srcs[base + j0 + lane] : 0;
            int np = (m + 1) >> 1;
            int p = 0;
            #pragma unroll 4
            for (; p + 1 < np; p += 2) {
                int ia = 2 * p + half;
                int ib = 2 * (p + 1) + half;
                int sa = __shfl_sync(0xffffffffu, s, ia);
                int sb = __shfl_sync(0xffffffffu, s, ib);
                float va = g_y[(size_t)sa * 16 + slot];
                float vb = g_y[(size_t)sb * 16 + slot];
                if (ia < m) acca += va;
                if (ib < m) accb += vb;
            }
            if (p < np) {
                int ia = 2 * p + half;
                int sa = __shfl_sync(0xffffffffu, s, ia);
                float va = g_y[(size_t)sa * 16 + slot];
                if (ia < m) acca += va;
            }
        }
        float acc = acca + accb;
        acc += __shfl_down_sync(0xffffffffu, acc, 16);
        float inv = 1.f / fmaxf((float)deg, 1.f);
        float o = acc * inv;
        if (lane < NCLS) o += g_z[(size_t)i * NCLS + lane];

        float ss = (lane < NCLS) ? o * o : 0.f;
        #pragma unroll
        for (int d = 16; d; d >>= 1) ss += __shfl_xor_sync(0xffffffffu, ss, d);
        float innorm = 1.f / fmaxf(sqrtf(ss), 1e-12f);
        o *= innorm;
        float mx = (lane < NCLS) ? o : -CUDART_INF_F;
        #pragma unroll
        for (int d = 16; d; d >>= 1) mx = fmaxf(mx, __shfl_xor_sync(0xffffffffu, mx, d));
        float ex = (lane < NCLS) ? expf(o - mx) : 0.f;
        float es = ex;
        #pragma unroll
        for (int d = 16; d; d >>= 1) es += __shfl_xor_sync(0xffffffffu, es, d);
        float lse = logf(es);
        if (lane < NCLS)
            out[(size_t)i * NCLS + lane] = (o - mx) - lse;
    }
}

extern "C" void kernel_launch(void* const* d_in, const int* in_sizes, int n_in,
                              void* d_out, int out_size) {
    const float* feat = (const float*)d_in[0];
    const void*  ei   = d_in[1];
    const float* W1l  = (const float*)d_in[2];
    const float* b1   = (const float*)d_in[3];
    const float* W1r  = (const float*)d_in[4];
    const float* W2l  = (const float*)d_in[5];
    const float* b2   = (const float*)d_in[6];
    const float* W2r  = (const float*)d_in[7];
    float* out = (float*)d_out;

    int N = in_sizes[0] / FEAT;
    int E = in_sizes[1] / 2;

    hist_kernel<<<(E + 255) / 256, 256>>>(ei, E, N);             // 1
    scan_kernel<<<SCAN_NB, 256>>>(N);                            // 2
    scatter_kernel<<<(E + 255) / 256, 256>>>(ei, E);             // 3
    l1gather_kernel<<<1184, 256>>>(feat, N);                     // 4 <- profiled
    l1mma_kernel<<<592, 128>>>(W1l, b1, W1r, W2l, b2, W2r, N);   // 5
    l2g_kernel<<<1184, 256>>>(out, N);                           // 6
}